// round 16
// baseline (speedup 1.0000x reference)
#include <cuda_runtime.h>

#define NN 1395
#define EE 44640
#define GB 592

// ---------------- scratch (device globals) ----------------------------------
__device__ __align__(16) float g_acc1[NN * 3 + 1];   // layer-1 aggregate
__device__ __align__(16) float g_acc2[NN * 3 + 1];   // layer-2 aggregate
__device__ int g_deg[NN];
__device__ unsigned g_pk[EE];
__device__ __align__(16) float g_v1[2048];
__device__ __align__(16) float g_v2[4096];
__device__ __align__(16) float g_c1[32 * 58 * 58];
__device__ __align__(16) float g_c2[32 * 54 * 54];
__device__ __align__(16) float g_c3[64 * 52 * 52];
__device__ __align__(16) float g_c4[64 * 50 * 50];
__device__ __align__(16) float g_f3[2048];
__device__ __align__(16) float g_f4[2048];

// ---------------- software grid barrier (used only inside kB) ----------------
__device__ unsigned g_cnt = 0;
__device__ volatile unsigned g_rel = 0;

__device__ __forceinline__ void gsync(unsigned nb) {
    __syncthreads();
    if (threadIdx.x == 0) {
        __threadfence();
        unsigned gen = g_rel;
        if (atomicAdd(&g_cnt, 1u) == nb - 1u) {
            g_cnt = 0u;
            __threadfence();
            g_rel = gen + 1u;
        } else {
            while (g_rel == gen) __nanosleep(64);
        }
    }
    __syncthreads();
}

__device__ __forceinline__ float warp_red(float a) {
#pragma unroll
    for (int o = 16; o > 0; o >>= 1)
        a += __shfl_down_sync(0xFFFFFFFFu, a, o);
    return a;
}

// ---------------- GCN recompute helpers (bitwise deterministic) --------------
__device__ __forceinline__ void xw1_of(const float* __restrict__ x,
                                       const float* __restrict__ W1,
                                       int s, float xw[3]) {
    float x3 = x[s * 6 + 3], x4 = x[s * 6 + 4], x5 = x[s * 6 + 5];
#pragma unroll
    for (int c = 0; c < 3; c++)
        xw[c] = x3 * W1[9 + c] + x4 * W1[12 + c] + x5 * W1[15 + c];
}

__device__ __forceinline__ void h_of(const float* __restrict__ x,
                                     const float* __restrict__ W1,
                                     const float* __restrict__ b1,
                                     int s, float ds2, float h[3]) {
    float xw[3];
    xw1_of(x, W1, s, xw);
#pragma unroll
    for (int c = 0; c < 3; c++) {
        float v = g_acc1[s * 3 + c] + ds2 * xw[c] + b1[c];
        h[c] = (v >= 0.f) ? v : 0.2f * v;
    }
}

// ---------------- edge pass: zero accs + seeds + dtype detect + pack ---------
__global__ void k_edge(const void* __restrict__ ei, const float* __restrict__ fc3_b,
                       const float* __restrict__ fc1_b, const float* __restrict__ fc2_b) {
    int e = blockIdx.x * 256 + threadIdx.x;
    if (e < 2048) { g_f3[e] = fc3_b[e]; g_v1[e] = fc1_b[e]; }
    if (e < 4096) g_v2[e] = fc2_b[e];
    if (e < NN * 3) { g_acc1[e] = 0.f; g_acc2[e] = 0.f; }
    const unsigned* u = (const unsigned*)ei;
    unsigned odd = (e < EE) ? u[2 * e + 1] : 0u;
    int any = __syncthreads_or(odd != 0u);    // int64 <=> odd dwords all zero
    int idx64 = !any;
    if (e >= EE) return;
    int s, d;
    if (idx64) {
        s = (int)((const long long*)ei)[e];
        d = (int)((const long long*)ei)[EE + e];
    } else {
        s = ((const int*)ei)[e];
        d = ((const int*)ei)[EE + e];
    }
    unsigned pk = 0xFFFFFFFFu;
    if (s >= 0 && s < NN && d >= 0 && d < NN) {
        pk = (unsigned)s | ((unsigned)d << 11);
        atomicAdd(&g_deg[d], 1);
    }
    g_pk[e] = pk;
}

// ---------------- scatter layer 1 (recomputes dinv, xw1 per edge) ------------
__global__ void k_scat1(const float* __restrict__ x, const float* __restrict__ W1) {
    int e = blockIdx.x * blockDim.x + threadIdx.x;
    if (e >= EE) return;
    unsigned pk = g_pk[e];
    if (pk == 0xFFFFFFFFu) return;
    int s = pk & 2047, d = pk >> 11;
    float ds = rsqrtf((float)(g_deg[s] + 1));
    float dd = rsqrtf((float)(g_deg[d] + 1));
    float xw[3];
    xw1_of(x, W1, s, xw);
    float n = ds * dd;
    atomicAdd(&g_acc1[d * 3 + 0], n * xw[0]);
    atomicAdd(&g_acc1[d * 3 + 1], n * xw[1]);
    atomicAdd(&g_acc1[d * 3 + 2], n * xw[2]);
}

// ---------------- scatter layer 2 (recomputes h, xw2 per edge) ---------------
__global__ void k_scat2(const float* __restrict__ x, const float* __restrict__ W1,
                        const float* __restrict__ b1, const float* __restrict__ W2) {
    int e = blockIdx.x * blockDim.x + threadIdx.x;
    if (e >= EE) return;
    unsigned pk = g_pk[e];
    if (pk == 0xFFFFFFFFu) return;
    int s = pk & 2047, d = pk >> 11;
    float ds = rsqrtf((float)(g_deg[s] + 1));
    float dd = rsqrtf((float)(g_deg[d] + 1));
    float h[3];
    h_of(x, W1, b1, s, ds * ds, h);
    float n = ds * dd;
#pragma unroll
    for (int c = 0; c < 3; c++) {
        float xw2 = h[0] * W2[c] + h[1] * W2[3 + c] + h[2] * W2[6 + c];
        atomicAdd(&g_acc2[d * 3 + c], n * xw2);
    }
}

// ---------------- fc1 [2048 x 4185]: 4 quarter-row warps, conflict-free LDS --
// xs reads use two aligned LDS.128 + warp-uniform component select (mis branch)
// instead of 4 scalar LDS with 4-way bank conflicts.
__global__ void k_fc1(const float* __restrict__ W,
                      const float* __restrict__ x, const float* __restrict__ W1,
                      const float* __restrict__ b1, const float* __restrict__ W2,
                      const float* __restrict__ b2) {
    __shared__ __align__(16) float xs[4196];   // 4185 + pad for q1 overread
    // recompute xs = leaky(acc2 + self2 + b2) per node (bitwise deterministic)
    for (int nidx = threadIdx.x; nidx < NN; nidx += 256) {
        float ds = rsqrtf((float)(g_deg[nidx] + 1));
        float ds2 = ds * ds;
        float h[3];
        h_of(x, W1, b1, nidx, ds2, h);
#pragma unroll
        for (int c = 0; c < 3; c++) {
            float xw2 = h[0] * W2[c] + h[1] * W2[3 + c] + h[2] * W2[6 + c];
            float v = g_acc2[nidx * 3 + c] + ds2 * xw2 + b2[c];
            xs[nidx * 3 + c] = (v >= 0.f) ? v : 0.2f * v;
        }
    }
    if (threadIdx.x < 11) xs[4185 + threadIdx.x] = 0.f;   // pad
    __syncthreads();
    int gt = blockIdx.x * 256 + threadIdx.x;
    int warp = gt >> 5, lane = gt & 31;
    int row = warp & 2047;
    int quart = warp >> 11;                 // 0..3
    const int qs[5] = {0, 1046, 2092, 3138, 4185};
    int start = qs[quart];
    int len = qs[quart + 1] - start;
    const float* base = W + (size_t)row * 4185 + start;
    int peel = (4 - ((row + start) & 3)) & 3;   // align W stream to 16B
    float a = 0.f;
    if (lane < peel) a += __ldcs(&base[lane]) * xs[start + lane];
    int nv4 = (len - peel) >> 2;
    const float4* b4 = (const float4*)(base + peel);
    int xoff = start + peel;
    int A = xoff >> 2, m2 = xoff & 3;
    const float4* xs4 = (const float4*)xs;
    if (m2 == 0) {
#pragma unroll 4
        for (int i = lane; i < nv4; i += 32) {
            float4 w = __ldcs(&b4[i]);
            float4 q = xs4[A + i];
            a += w.x * q.x + w.y * q.y + w.z * q.z + w.w * q.w;
        }
    } else if (m2 == 1) {
#pragma unroll 4
        for (int i = lane; i < nv4; i += 32) {
            float4 w = __ldcs(&b4[i]);
            float4 q0 = xs4[A + i];
            float4 q1 = xs4[A + i + 1];
            a += w.x * q0.y + w.y * q0.z + w.z * q0.w + w.w * q1.x;
        }
    } else if (m2 == 2) {
#pragma unroll 4
        for (int i = lane; i < nv4; i += 32) {
            float4 w = __ldcs(&b4[i]);
            float4 q0 = xs4[A + i];
            float4 q1 = xs4[A + i + 1];
            a += w.x * q0.z + w.y * q0.w + w.z * q1.x + w.w * q1.y;
        }
    } else {
#pragma unroll 4
        for (int i = lane; i < nv4; i += 32) {
            float4 w = __ldcs(&b4[i]);
            float4 q0 = xs4[A + i];
            float4 q1 = xs4[A + i + 1];
            a += w.x * q0.w + w.y * q1.x + w.z * q1.y + w.w * q1.z;
        }
    }
    int tail = len - peel - (nv4 << 2);
    if (lane < tail) {
        int ti = peel + (nv4 << 2) + lane;
        a += __ldcs(&base[ti]) * xs[start + ti];
    }
    a = warp_red(a);
    if (lane == 0) atomicAdd(&g_v1[row], a);
}

// ---------------- fc2 [4096 x 2048]: 2 half-row warps per row ----------------
__global__ void k_fc2(const float* __restrict__ W,
                      const float* __restrict__ c2_b, const float* __restrict__ c3_b,
                      const float* __restrict__ c4_b) {
    __shared__ __align__(16) float xs[2048];
    {
        int gt = blockIdx.x * 256 + threadIdx.x;
        int T = gridDim.x * 256;
        for (int i = gt; i < NN; i += T) g_deg[i] = 0;   // ready for next replay
        for (int i = gt; i < 32 * 54 * 54; i += T) g_c2[i] = c2_b[i / (54 * 54)];
        for (int i = gt; i < 64 * 52 * 52; i += T) g_c3[i] = c3_b[i / (52 * 52)];
        for (int i = gt; i < 64 * 50 * 50; i += T) g_c4[i] = c4_b[i / (50 * 50)];
    }
    for (int i = threadIdx.x; i < 2048; i += 256) xs[i] = g_v1[i];
    __syncthreads();
    int gt = blockIdx.x * 256 + threadIdx.x;
    int warp = gt >> 5, lane = gt & 31;
    int row = warp & 4095;
    int half = warp >> 12;                 // 0 or 1
    int c0 = half * 256;                   // float4 column offset
    const float4* w4 = (const float4*)(W + (size_t)row * 2048) + c0;
    const float4* xs4 = (const float4*)xs + c0;
    float a = 0.f;
#pragma unroll 4
    for (int i = lane; i < 256; i += 32) {
        float4 w = __ldcs(&w4[i]);
        float4 xv = xs4[i];
        a += w.x * xv.x + w.y * xv.y + w.z * xv.z + w.w * xv.w;
    }
    a = warp_red(a);
    if (lane == 0) atomicAdd(&g_v2[row], a);
}

// ---------------- conv (CI-split, REDG accumulation) -------------------------
template <int CI, int KH, int KW, int OCB, int SPLIT>
__device__ __forceinline__ void conv_impl(const float* __restrict__ in,
                                          const float* __restrict__ w,
                                          const float* __restrict__ bia,
                                          float* __restrict__ out,
                                          int H, int W, int OH, int OW) {
    const int CIP = CI / SPLIT;
    __shared__ float sw[OCB * CIP * KH * KW];
    int ocg = blockIdx.x / SPLIT;
    int part = blockIdx.x - ocg * SPLIT;
    int oc0 = ocg * OCB;
    int ic0 = part * CIP;
    for (int i = threadIdx.x; i < OCB * CIP * KH * KW; i += blockDim.x) {
        int o = i / (CIP * KH * KW);
        int rem = i - o * (CIP * KH * KW);
        int ic = rem / (KH * KW);
        int k = rem - ic * (KH * KW);
        sw[i] = w[((size_t)(oc0 + o) * CI + ic0 + ic) * (KH * KW) + k];
    }
    __syncthreads();

    int p = blockIdx.y * blockDim.x + threadIdx.x;
    if (p >= OH * OW) return;
    int oy = p / OW, ox = p - oy * OW;
    float acc[OCB];
#pragma unroll
    for (int o = 0; o < OCB; o++) acc[o] = (SPLIT == 1) ? bia[oc0 + o] : 0.f;

    for (int ic = 0; ic < CIP; ic++) {
        const float* ip = in + ((size_t)(ic0 + ic) * H + oy) * W + ox;
        const float* wp = sw + ic * KH * KW;
#pragma unroll
        for (int i = 0; i < KH; i++)
#pragma unroll
            for (int j = 0; j < KW; j++) {
                float v = ip[i * W + j];
#pragma unroll
                for (int o = 0; o < OCB; o++)
                    acc[o] += wp[o * CIP * KH * KW + i * KW + j] * v;
            }
    }
#pragma unroll
    for (int o = 0; o < OCB; o++) {
        size_t oi = ((size_t)(oc0 + o) * OH + oy) * OW + ox;
        if (SPLIT == 1) out[oi] = acc[o];
        else atomicAdd(&out[oi], acc[o]);
    }
}

__global__ void k_conv1(const float* __restrict__ w, const float* __restrict__ b) {
    conv_impl<1, 7, 7, 4, 1>(g_v2, w, b, g_c1, 64, 64, 58, 58);
}
__global__ void k_conv2(const float* __restrict__ w, const float* __restrict__ b) {
    conv_impl<32, 5, 5, 4, 4>(g_c1, w, b, g_c2, 58, 58, 54, 54);
}
__global__ void k_conv3(const float* __restrict__ w, const float* __restrict__ b) {
    conv_impl<32, 3, 3, 8, 2>(g_c2, w, b, g_c3, 54, 54, 52, 52);
}
__global__ void k_conv4(const float* __restrict__ w, const float* __restrict__ b) {
    conv_impl<64, 3, 3, 8, 4>(g_c3, w, b, g_c4, 52, 52, 50, 50);
}

// ---------------- kB: fc3 (8-row groups, proven) + fc4 + fc5 -----------------
extern "C" __global__ void __launch_bounds__(256, 4) kB(
    const float* __restrict__ fc3_w,
    const float* __restrict__ fc4_w, const float* __restrict__ fc4_b,
    const float* __restrict__ fc5_w, const float* __restrict__ fc5_b,
    float* __restrict__ out) {
    __shared__ __align__(16) float xs[2048];
    __shared__ float sred[8];

    // fc3: 2048x160000. 4096 chunks = 256 row-groups(8 rows) x 16 col-splits.
    const int NC4 = 40000, CHUNK = 2500, NCHUNK = 4096;
    for (int c = blockIdx.x; c < NCHUNK; c += GB) {
        int rg = c >> 4, cs = c & 15;
        int r0 = rg * 8;
        if (threadIdx.x < 8) sred[threadIdx.x] = 0.f;
        __syncthreads();
        const float4* x4 = (const float4*)g_c4 + cs * CHUNK;
        const float4* w4 = (const float4*)fc3_w + (size_t)r0 * NC4 + cs * CHUNK;
        float a[8];
#pragma unroll
        for (int k = 0; k < 8; k++) a[k] = 0.f;
        for (int i = threadIdx.x; i < CHUNK; i += 256) {
            float4 xv = x4[i];
#pragma unroll
            for (int k = 0; k < 8; k++) {
                float4 w = __ldcs(&w4[i + k * NC4]);
                a[k] += w.x * xv.x + w.y * xv.y + w.z * xv.z + w.w * xv.w;
            }
        }
#pragma unroll
        for (int k = 0; k < 8; k++) a[k] = warp_red(a[k]);
        if ((threadIdx.x & 31) == 0) {
#pragma unroll
            for (int k = 0; k < 8; k++) atomicAdd(&sred[k], a[k]);
        }
        __syncthreads();
        if (threadIdx.x < 8) atomicAdd(&g_f3[r0 + threadIdx.x], sred[threadIdx.x]);
        __syncthreads();
    }
    gsync(GB);

    // fc4: 2048x2048, warp per row
    {
        for (int i = threadIdx.x; i < 2048; i += 256) xs[i] = __ldcg(&g_f3[i]);
        __syncthreads();
        int gt = blockIdx.x * 256 + threadIdx.x;
        int warp = gt >> 5, lane = gt & 31, nwarp = (GB * 256) >> 5;
        const float4* xs4 = (const float4*)xs;
        for (int r = warp; r < 2048; r += nwarp) {
            const float4* w4 = (const float4*)(fc4_w + (size_t)r * 2048);
            float a = 0.f;
#pragma unroll 4
            for (int i = lane; i < 512; i += 32) {
                float4 w = __ldcs(&w4[i]);
                float4 xv = xs4[i];
                a += w.x * xv.x + w.y * xv.y + w.z * xv.z + w.w * xv.w;
            }
            a = warp_red(a);
            if (lane == 0) g_f4[r] = a + fc4_b[r];
        }
    }
    gsync(GB);

    // fc5: 48x2048 -> out
    {
        for (int i = threadIdx.x; i < 2048; i += 256) xs[i] = __ldcg(&g_f4[i]);
        __syncthreads();
        int gt = blockIdx.x * 256 + threadIdx.x;
        int warp = gt >> 5, lane = gt & 31;
        if (warp < 48) {
            const float4* w4 = (const float4*)(fc5_w + (size_t)warp * 2048);
            const float4* xs4 = (const float4*)xs;
            float a = 0.f;
            for (int i = lane; i < 512; i += 32) {
                float4 w = w4[i];
                float4 xv = xs4[i];
                a += w.x * xv.x + w.y * xv.y + w.z * xv.z + w.w * xv.w;
            }
            a = warp_red(a);
            if (lane == 0) out[warp] = a + fc5_b[warp];
        }
    }
}

// ---------------- launcher ---------------------------------------------------
extern "C" void kernel_launch(void* const* d_in, const int* in_sizes, int n_in,
                              void* d_out, int out_size) {
    const float* x     = (const float*)d_in[0];
    const void*  ei    = d_in[1];
    const float* W1    = (const float*)d_in[2];
    const float* b1    = (const float*)d_in[3];
    const float* W2    = (const float*)d_in[4];
    const float* b2    = (const float*)d_in[5];
    const float* fc1_w = (const float*)d_in[6];
    const float* fc1_b = (const float*)d_in[7];
    const float* fc2_w = (const float*)d_in[8];
    const float* fc2_b = (const float*)d_in[9];
    const float* c1_w  = (const float*)d_in[10];
    const float* c1_b  = (const float*)d_in[11];
    const float* c2_w  = (const float*)d_in[12];
    const float* c2_b  = (const float*)d_in[13];
    const float* c3_w  = (const float*)d_in[14];
    const float* c3_b  = (const float*)d_in[15];
    const float* c4_w  = (const float*)d_in[16];
    const float* c4_b  = (const float*)d_in[17];
    const float* fc3_w = (const float*)d_in[18];
    const float* fc3_b = (const float*)d_in[19];
    const float* fc4_w = (const float*)d_in[20];
    const float* fc4_b = (const float*)d_in[21];
    const float* fc5_w = (const float*)d_in[22];
    const float* fc5_b = (const float*)d_in[23];
    float* out = (float*)d_out;

    const int NB_E = (EE + 255) / 256;

    k_edge<<<NB_E, 256>>>(ei, fc3_b, fc1_b, fc2_b);
    k_scat1<<<NB_E, 256>>>(x, W1);
    k_scat2<<<NB_E, 256>>>(x, W1, b1, W2);

    k_fc1<<<1024, 256>>>(fc1_w, x, W1, b1, W2, b2);
    k_fc2<<<1024, 256>>>(fc2_w, c2_b, c3_b, c4_b);

    {
        dim3 g1(8, (58 * 58 + 255) / 256);
        k_conv1<<<g1, 256>>>(c1_w, c1_b);
        dim3 g2(32, (54 * 54 + 255) / 256);
        k_conv2<<<g2, 256>>>(c2_w, c2_b);
        dim3 g3(16, (52 * 52 + 255) / 256);
        k_conv3<<<g3, 256>>>(c3_w, c3_b);
        dim3 g4(32, (50 * 50 + 255) / 256);
        k_conv4<<<g4, 256>>>(c4_w, c4_b);
    }

    kB<<<GB, 256>>>(fc3_w, fc4_w, fc4_b, fc5_w, fc5_b, out);
}

// round 17
// speedup vs baseline: 1.0375x; 1.0375x over previous
#include <cuda_runtime.h>

#define NN 1395
#define EE 44640
#define GB 592

// ---------------- scratch (device globals) ----------------------------------
__device__ __align__(16) float g_acc1[NN * 3 + 1];   // layer-1 aggregate
__device__ __align__(16) float g_acc2[NN * 3 + 1];   // layer-2 aggregate
__device__ int g_deg[NN];
__device__ unsigned g_pk[EE];
__device__ __align__(16) float g_v1[2048];
__device__ __align__(16) float g_v2[4096];
__device__ __align__(16) float g_c1[32 * 58 * 58];
__device__ __align__(16) float g_c2[32 * 54 * 54];
__device__ __align__(16) float g_c3[64 * 52 * 52];
__device__ __align__(16) float g_c4[64 * 50 * 50];
__device__ __align__(16) float g_f3[2048];
__device__ __align__(16) float g_f4[2048];

// ---------------- software grid barrier (used only inside kB) ----------------
__device__ unsigned g_cnt = 0;
__device__ volatile unsigned g_rel = 0;

__device__ __forceinline__ void gsync(unsigned nb) {
    __syncthreads();
    if (threadIdx.x == 0) {
        __threadfence();
        unsigned gen = g_rel;
        if (atomicAdd(&g_cnt, 1u) == nb - 1u) {
            g_cnt = 0u;
            __threadfence();
            g_rel = gen + 1u;
        } else {
            while (g_rel == gen) __nanosleep(64);
        }
    }
    __syncthreads();
}

__device__ __forceinline__ float warp_red(float a) {
#pragma unroll
    for (int o = 16; o > 0; o >>= 1)
        a += __shfl_down_sync(0xFFFFFFFFu, a, o);
    return a;
}

// ---------------- GCN recompute helpers (bitwise deterministic) --------------
__device__ __forceinline__ void xw1_of(const float* __restrict__ x,
                                       const float* __restrict__ W1,
                                       int s, float xw[3]) {
    float x3 = x[s * 6 + 3], x4 = x[s * 6 + 4], x5 = x[s * 6 + 5];
#pragma unroll
    for (int c = 0; c < 3; c++)
        xw[c] = x3 * W1[9 + c] + x4 * W1[12 + c] + x5 * W1[15 + c];
}

__device__ __forceinline__ void h_of(const float* __restrict__ x,
                                     const float* __restrict__ W1,
                                     const float* __restrict__ b1,
                                     int s, float ds2, float h[3]) {
    float xw[3];
    xw1_of(x, W1, s, xw);
#pragma unroll
    for (int c = 0; c < 3; c++) {
        float v = g_acc1[s * 3 + c] + ds2 * xw[c] + b1[c];
        h[c] = (v >= 0.f) ? v : 0.2f * v;
    }
}

// ---------------- edge pass: zero accs + seeds + dtype detect + pack ---------
__global__ void k_edge(const void* __restrict__ ei, const float* __restrict__ fc3_b,
                       const float* __restrict__ fc1_b, const float* __restrict__ fc2_b) {
    int e = blockIdx.x * 256 + threadIdx.x;
    if (e < 2048) { g_f3[e] = fc3_b[e]; g_v1[e] = fc1_b[e]; }
    if (e < 4096) g_v2[e] = fc2_b[e];
    if (e < NN * 3) { g_acc1[e] = 0.f; g_acc2[e] = 0.f; }
    const unsigned* u = (const unsigned*)ei;
    unsigned odd = (e < EE) ? u[2 * e + 1] : 0u;
    int any = __syncthreads_or(odd != 0u);    // int64 <=> odd dwords all zero
    int idx64 = !any;
    if (e >= EE) return;
    int s, d;
    if (idx64) {
        s = (int)((const long long*)ei)[e];
        d = (int)((const long long*)ei)[EE + e];
    } else {
        s = ((const int*)ei)[e];
        d = ((const int*)ei)[EE + e];
    }
    unsigned pk = 0xFFFFFFFFu;
    if (s >= 0 && s < NN && d >= 0 && d < NN) {
        pk = (unsigned)s | ((unsigned)d << 11);
        atomicAdd(&g_deg[d], 1);
    }
    g_pk[e] = pk;
}

// ---------------- scatter layer 1 (recomputes dinv, xw1 per edge) ------------
__global__ void k_scat1(const float* __restrict__ x, const float* __restrict__ W1) {
    int e = blockIdx.x * blockDim.x + threadIdx.x;
    if (e >= EE) return;
    unsigned pk = g_pk[e];
    if (pk == 0xFFFFFFFFu) return;
    int s = pk & 2047, d = pk >> 11;
    float ds = rsqrtf((float)(g_deg[s] + 1));
    float dd = rsqrtf((float)(g_deg[d] + 1));
    float xw[3];
    xw1_of(x, W1, s, xw);
    float n = ds * dd;
    atomicAdd(&g_acc1[d * 3 + 0], n * xw[0]);
    atomicAdd(&g_acc1[d * 3 + 1], n * xw[1]);
    atomicAdd(&g_acc1[d * 3 + 2], n * xw[2]);
}

// ---------------- scatter layer 2 (recomputes h, xw2 per edge) ---------------
__global__ void k_scat2(const float* __restrict__ x, const float* __restrict__ W1,
                        const float* __restrict__ b1, const float* __restrict__ W2) {
    int e = blockIdx.x * blockDim.x + threadIdx.x;
    if (e >= EE) return;
    unsigned pk = g_pk[e];
    if (pk == 0xFFFFFFFFu) return;
    int s = pk & 2047, d = pk >> 11;
    float ds = rsqrtf((float)(g_deg[s] + 1));
    float dd = rsqrtf((float)(g_deg[d] + 1));
    float h[3];
    h_of(x, W1, b1, s, ds * ds, h);
    float n = ds * dd;
#pragma unroll
    for (int c = 0; c < 3; c++) {
        float xw2 = h[0] * W2[c] + h[1] * W2[3 + c] + h[2] * W2[6 + c];
        atomicAdd(&g_acc2[d * 3 + c], n * xw2);
    }
}

// ---------------- fc1 [2048 x 4185]: 2 half-row warps, conflict-free LDS -----
// xs reads: two aligned LDS.128 + warp-uniform component window select.
__global__ void k_fc1(const float* __restrict__ W,
                      const float* __restrict__ x, const float* __restrict__ W1,
                      const float* __restrict__ b1, const float* __restrict__ W2,
                      const float* __restrict__ b2) {
    __shared__ __align__(16) float xs[4196];   // 4185 + pad for q1 overread
    // recompute xs = leaky(acc2 + self2 + b2) per node (bitwise deterministic)
    for (int nidx = threadIdx.x; nidx < NN; nidx += 256) {
        float ds = rsqrtf((float)(g_deg[nidx] + 1));
        float ds2 = ds * ds;
        float h[3];
        h_of(x, W1, b1, nidx, ds2, h);
#pragma unroll
        for (int c = 0; c < 3; c++) {
            float xw2 = h[0] * W2[c] + h[1] * W2[3 + c] + h[2] * W2[6 + c];
            float v = g_acc2[nidx * 3 + c] + ds2 * xw2 + b2[c];
            xs[nidx * 3 + c] = (v >= 0.f) ? v : 0.2f * v;
        }
    }
    if (threadIdx.x < 11) xs[4185 + threadIdx.x] = 0.f;   // pad
    __syncthreads();
    int gt = blockIdx.x * 256 + threadIdx.x;
    int warp = gt >> 5, lane = gt & 31;
    int row = warp & 2047;
    int half = warp >> 11;                 // 0 or 1
    int start = half ? 2093 : 0;
    int len = half ? (4185 - 2093) : 2093;
    const float* base = W + (size_t)row * 4185 + start;
    int peel = (4 - ((row + start) & 3)) & 3;   // align W stream to 16B
    float a = 0.f;
    if (lane < peel) a += __ldcs(&base[lane]) * xs[start + lane];
    int nv4 = (len - peel) >> 2;
    const float4* b4 = (const float4*)(base + peel);
    int xoff = start + peel;
    int A = xoff >> 2, m2 = xoff & 3;
    const float4* xs4 = (const float4*)xs;
    if (m2 == 0) {
#pragma unroll 4
        for (int i = lane; i < nv4; i += 32) {
            float4 w = __ldcs(&b4[i]);
            float4 q = xs4[A + i];
            a += w.x * q.x + w.y * q.y + w.z * q.z + w.w * q.w;
        }
    } else if (m2 == 1) {
#pragma unroll 4
        for (int i = lane; i < nv4; i += 32) {
            float4 w = __ldcs(&b4[i]);
            float4 q0 = xs4[A + i];
            float4 q1 = xs4[A + i + 1];
            a += w.x * q0.y + w.y * q0.z + w.z * q0.w + w.w * q1.x;
        }
    } else if (m2 == 2) {
#pragma unroll 4
        for (int i = lane; i < nv4; i += 32) {
            float4 w = __ldcs(&b4[i]);
            float4 q0 = xs4[A + i];
            float4 q1 = xs4[A + i + 1];
            a += w.x * q0.z + w.y * q0.w + w.z * q1.x + w.w * q1.y;
        }
    } else {
#pragma unroll 4
        for (int i = lane; i < nv4; i += 32) {
            float4 w = __ldcs(&b4[i]);
            float4 q0 = xs4[A + i];
            float4 q1 = xs4[A + i + 1];
            a += w.x * q0.w + w.y * q1.x + w.z * q1.y + w.w * q1.z;
        }
    }
    int tail = len - peel - (nv4 << 2);
    if (lane < tail) {
        int ti = peel + (nv4 << 2) + lane;
        a += __ldcs(&base[ti]) * xs[start + ti];
    }
    a = warp_red(a);
    if (lane == 0) atomicAdd(&g_v1[row], a);
}

// ---------------- fc2 [4096 x 2048]: 2 half-row warps per row ----------------
__global__ void k_fc2(const float* __restrict__ W,
                      const float* __restrict__ c2_b, const float* __restrict__ c3_b,
                      const float* __restrict__ c4_b) {
    __shared__ __align__(16) float xs[2048];
    {
        int gt = blockIdx.x * 256 + threadIdx.x;
        int T = gridDim.x * 256;
        for (int i = gt; i < NN; i += T) g_deg[i] = 0;   // ready for next replay
        for (int i = gt; i < 32 * 54 * 54; i += T) g_c2[i] = c2_b[i / (54 * 54)];
        for (int i = gt; i < 64 * 52 * 52; i += T) g_c3[i] = c3_b[i / (52 * 52)];
        for (int i = gt; i < 64 * 50 * 50; i += T) g_c4[i] = c4_b[i / (50 * 50)];
    }
    for (int i = threadIdx.x; i < 2048; i += 256) xs[i] = g_v1[i];
    __syncthreads();
    int gt = blockIdx.x * 256 + threadIdx.x;
    int warp = gt >> 5, lane = gt & 31;
    int row = warp & 4095;
    int half = warp >> 12;                 // 0 or 1
    int c0 = half * 256;                   // float4 column offset
    const float4* w4 = (const float4*)(W + (size_t)row * 2048) + c0;
    const float4* xs4 = (const float4*)xs + c0;
    float a = 0.f;
#pragma unroll 4
    for (int i = lane; i < 256; i += 32) {
        float4 w = __ldcs(&w4[i]);
        float4 xv = xs4[i];
        a += w.x * xv.x + w.y * xv.y + w.z * xv.z + w.w * xv.w;
    }
    a = warp_red(a);
    if (lane == 0) atomicAdd(&g_v2[row], a);
}

// ---------------- conv (CI-split, REDG accumulation) -------------------------
template <int CI, int KH, int KW, int OCB, int SPLIT>
__device__ __forceinline__ void conv_impl(const float* __restrict__ in,
                                          const float* __restrict__ w,
                                          const float* __restrict__ bia,
                                          float* __restrict__ out,
                                          int H, int W, int OH, int OW) {
    const int CIP = CI / SPLIT;
    __shared__ float sw[OCB * CIP * KH * KW];
    int ocg = blockIdx.x / SPLIT;
    int part = blockIdx.x - ocg * SPLIT;
    int oc0 = ocg * OCB;
    int ic0 = part * CIP;
    for (int i = threadIdx.x; i < OCB * CIP * KH * KW; i += blockDim.x) {
        int o = i / (CIP * KH * KW);
        int rem = i - o * (CIP * KH * KW);
        int ic = rem / (KH * KW);
        int k = rem - ic * (KH * KW);
        sw[i] = w[((size_t)(oc0 + o) * CI + ic0 + ic) * (KH * KW) + k];
    }
    __syncthreads();

    int p = blockIdx.y * blockDim.x + threadIdx.x;
    if (p >= OH * OW) return;
    int oy = p / OW, ox = p - oy * OW;
    float acc[OCB];
#pragma unroll
    for (int o = 0; o < OCB; o++) acc[o] = (SPLIT == 1) ? bia[oc0 + o] : 0.f;

    for (int ic = 0; ic < CIP; ic++) {
        const float* ip = in + ((size_t)(ic0 + ic) * H + oy) * W + ox;
        const float* wp = sw + ic * KH * KW;
#pragma unroll
        for (int i = 0; i < KH; i++)
#pragma unroll
            for (int j = 0; j < KW; j++) {
                float v = ip[i * W + j];
#pragma unroll
                for (int o = 0; o < OCB; o++)
                    acc[o] += wp[o * CIP * KH * KW + i * KW + j] * v;
            }
    }
#pragma unroll
    for (int o = 0; o < OCB; o++) {
        size_t oi = ((size_t)(oc0 + o) * OH + oy) * OW + ox;
        if (SPLIT == 1) out[oi] = acc[o];
        else atomicAdd(&out[oi], acc[o]);
    }
}

__global__ void k_conv1(const float* __restrict__ w, const float* __restrict__ b) {
    conv_impl<1, 7, 7, 4, 1>(g_v2, w, b, g_c1, 64, 64, 58, 58);
}
__global__ void k_conv2(const float* __restrict__ w, const float* __restrict__ b) {
    conv_impl<32, 5, 5, 4, 4>(g_c1, w, b, g_c2, 58, 58, 54, 54);
}
__global__ void k_conv3(const float* __restrict__ w, const float* __restrict__ b) {
    conv_impl<32, 3, 3, 8, 2>(g_c2, w, b, g_c3, 54, 54, 52, 52);
}
__global__ void k_conv4(const float* __restrict__ w, const float* __restrict__ b) {
    conv_impl<64, 3, 3, 8, 4>(g_c3, w, b, g_c4, 52, 52, 50, 50);
}

// ---------------- kB: fc3 (8-row groups, proven) + fc4 + fc5 -----------------
extern "C" __global__ void __launch_bounds__(256, 4) kB(
    const float* __restrict__ fc3_w,
    const float* __restrict__ fc4_w, const float* __restrict__ fc4_b,
    const float* __restrict__ fc5_w, const float* __restrict__ fc5_b,
    float* __restrict__ out) {
    __shared__ __align__(16) float xs[2048];
    __shared__ float sred[8];

    // fc3: 2048x160000. 4096 chunks = 256 row-groups(8 rows) x 16 col-splits.
    const int NC4 = 40000, CHUNK = 2500, NCHUNK = 4096;
    for (int c = blockIdx.x; c < NCHUNK; c += GB) {
        int rg = c >> 4, cs = c & 15;
        int r0 = rg * 8;
        if (threadIdx.x < 8) sred[threadIdx.x] = 0.f;
        __syncthreads();
        const float4* x4 = (const float4*)g_c4 + cs * CHUNK;
        const float4* w4 = (const float4*)fc3_w + (size_t)r0 * NC4 + cs * CHUNK;
        float a[8];
#pragma unroll
        for (int k = 0; k < 8; k++) a[k] = 0.f;
        for (int i = threadIdx.x; i < CHUNK; i += 256) {
            float4 xv = x4[i];
#pragma unroll
            for (int k = 0; k < 8; k++) {
                float4 w = __ldcs(&w4[i + k * NC4]);
                a[k] += w.x * xv.x + w.y * xv.y + w.z * xv.z + w.w * xv.w;
            }
        }
#pragma unroll
        for (int k = 0; k < 8; k++) a[k] = warp_red(a[k]);
        if ((threadIdx.x & 31) == 0) {
#pragma unroll
            for (int k = 0; k < 8; k++) atomicAdd(&sred[k], a[k]);
        }
        __syncthreads();
        if (threadIdx.x < 8) atomicAdd(&g_f3[r0 + threadIdx.x], sred[threadIdx.x]);
        __syncthreads();
    }
    gsync(GB);

    // fc4: 2048x2048, warp per row
    {
        for (int i = threadIdx.x; i < 2048; i += 256) xs[i] = __ldcg(&g_f3[i]);
        __syncthreads();
        int gt = blockIdx.x * 256 + threadIdx.x;
        int warp = gt >> 5, lane = gt & 31, nwarp = (GB * 256) >> 5;
        const float4* xs4 = (const float4*)xs;
        for (int r = warp; r < 2048; r += nwarp) {
            const float4* w4 = (const float4*)(fc4_w + (size_t)r * 2048);
            float a = 0.f;
#pragma unroll 4
            for (int i = lane; i < 512; i += 32) {
                float4 w = __ldcs(&w4[i]);
                float4 xv = xs4[i];
                a += w.x * xv.x + w.y * xv.y + w.z * xv.z + w.w * xv.w;
            }
            a = warp_red(a);
            if (lane == 0) g_f4[r] = a + fc4_b[r];
        }
    }
    gsync(GB);

    // fc5: 48x2048 -> out
    {
        for (int i = threadIdx.x; i < 2048; i += 256) xs[i] = __ldcg(&g_f4[i]);
        __syncthreads();
        int gt = blockIdx.x * 256 + threadIdx.x;
        int warp = gt >> 5, lane = gt & 31;
        if (warp < 48) {
            const float4* w4 = (const float4*)(fc5_w + (size_t)warp * 2048);
            const float4* xs4 = (const float4*)xs;
            float a = 0.f;
            for (int i = lane; i < 512; i += 32) {
                float4 w = w4[i];
                float4 xv = xs4[i];
                a += w.x * xv.x + w.y * xv.y + w.z * xv.z + w.w * xv.w;
            }
            a = warp_red(a);
            if (lane == 0) out[warp] = a + fc5_b[warp];
        }
    }
}

// ---------------- launcher ---------------------------------------------------
extern "C" void kernel_launch(void* const* d_in, const int* in_sizes, int n_in,
                              void* d_out, int out_size) {
    const float* x     = (const float*)d_in[0];
    const void*  ei    = d_in[1];
    const float* W1    = (const float*)d_in[2];
    const float* b1    = (const float*)d_in[3];
    const float* W2    = (const float*)d_in[4];
    const float* b2    = (const float*)d_in[5];
    const float* fc1_w = (const float*)d_in[6];
    const float* fc1_b = (const float*)d_in[7];
    const float* fc2_w = (const float*)d_in[8];
    const float* fc2_b = (const float*)d_in[9];
    const float* c1_w  = (const float*)d_in[10];
    const float* c1_b  = (const float*)d_in[11];
    const float* c2_w  = (const float*)d_in[12];
    const float* c2_b  = (const float*)d_in[13];
    const float* c3_w  = (const float*)d_in[14];
    const float* c3_b  = (const float*)d_in[15];
    const float* c4_w  = (const float*)d_in[16];
    const float* c4_b  = (const float*)d_in[17];
    const float* fc3_w = (const float*)d_in[18];
    const float* fc3_b = (const float*)d_in[19];
    const float* fc4_w = (const float*)d_in[20];
    const float* fc4_b = (const float*)d_in[21];
    const float* fc5_w = (const float*)d_in[22];
    const float* fc5_b = (const float*)d_in[23];
    float* out = (float*)d_out;

    const int NB_E = (EE + 255) / 256;

    k_edge<<<NB_E, 256>>>(ei, fc3_b, fc1_b, fc2_b);
    k_scat1<<<NB_E, 256>>>(x, W1);
    k_scat2<<<NB_E, 256>>>(x, W1, b1, W2);

    k_fc1<<<512, 256>>>(fc1_w, x, W1, b1, W2, b2);
    k_fc2<<<1024, 256>>>(fc2_w, c2_b, c3_b, c4_b);

    {
        dim3 g1(8, (58 * 58 + 255) / 256);
        k_conv1<<<g1, 256>>>(c1_w, c1_b);
        dim3 g2(32, (54 * 54 + 255) / 256);
        k_conv2<<<g2, 256>>>(c2_w, c2_b);
        dim3 g3(16, (52 * 52 + 255) / 256);
        k_conv3<<<g3, 256>>>(c3_w, c3_b);
        dim3 g4(32, (50 * 50 + 255) / 256);
        k_conv4<<<g4, 256>>>(c4_w, c4_b);
    }

    kB<<<GB, 256>>>(fc3_w, fc4_w, fc4_b, fc5_w, fc5_b, out);
}